// round 7
// baseline (speedup 1.0000x reference)
#include <cuda_runtime.h>
#include <cuda_bf16.h>
#include <cstdint>

// Problem constants (fixed shapes per reference)
#define NTOK  (32 * 8192)   // 262144 tokens
#define DIM   256           // K
#define NEXP  16
#define POUT  64            // N
#define BM    256           // tokens per tile
#define CK    64            // K per chunk
#define NCH   (DIM / CK)    // 4 chunks

// ---------------- scratch ----------------
__device__ int g_sorted[NEXP][NTOK];   // per-expert slot regions (16 MB)
__device__ int g_cursor[NEXP];
// Pre-split W tiles, bf16 hi/lo, in swizzled tile byte order.
__device__ unsigned char g_Whi[NEXP][NCH][8192];
__device__ unsigned char g_Wlo[NEXP][NCH][8192];

// ---------------- helpers ----------------
__device__ __forceinline__ uint32_t s2u(const void* p) {
    uint32_t a;
    asm("{ .reg .u64 t; cvta.to.shared.u64 t, %1; cvt.u32.u64 %0, t; }" : "=r"(a) : "l"(p));
    return a;
}
__device__ __forceinline__ uint32_t sw128(uint32_t o) { return o ^ ((o >> 3) & 0x70); }

__device__ __forceinline__ void ldsm_x4(uint32_t addr, uint32_t r[4]) {
    asm volatile("ldmatrix.sync.aligned.m8n8.x4.shared.b16 {%0,%1,%2,%3}, [%4];"
                 : "=r"(r[0]), "=r"(r[1]), "=r"(r[2]), "=r"(r[3]) : "r"(addr));
}
__device__ __forceinline__ void ldsm_x4_t(uint32_t addr, uint32_t r[4]) {
    asm volatile("ldmatrix.sync.aligned.m8n8.x4.trans.shared.b16 {%0,%1,%2,%3}, [%4];"
                 : "=r"(r[0]), "=r"(r[1]), "=r"(r[2]), "=r"(r[3]) : "r"(addr));
}
__device__ __forceinline__ void mma16816(float c[4], const uint32_t a[4],
                                         uint32_t b0, uint32_t b1) {
    asm volatile(
        "mma.sync.aligned.m16n8k16.row.col.f32.bf16.bf16.f32 "
        "{%0,%1,%2,%3}, {%4,%5,%6,%7}, {%8,%9}, {%0,%1,%2,%3};"
        : "+f"(c[0]), "+f"(c[1]), "+f"(c[2]), "+f"(c[3])
        : "r"(a[0]), "r"(a[1]), "r"(a[2]), "r"(a[3]), "r"(b0), "r"(b1));
}
__device__ __forceinline__ void cpasync16(uint32_t dst, const void* src) {
    asm volatile("cp.async.cg.shared.global [%0], [%1], 16;"
                 :: "r"(dst), "l"(src) : "memory");
}

// split fp32 float4 -> packed bf16 hi (truncated, exact bits) + bf16 lo (residual)
__device__ __forceinline__ void split4(float4 f, uint2& hv, uint2& lv) {
    uint32_t bx = __float_as_uint(f.x), by = __float_as_uint(f.y);
    uint32_t bz = __float_as_uint(f.z), bw = __float_as_uint(f.w);
    hv.x = __byte_perm(bx, by, 0x7632);
    hv.y = __byte_perm(bz, bw, 0x7632);
    float lx = f.x - __uint_as_float(bx & 0xFFFF0000u);
    float ly = f.y - __uint_as_float(by & 0xFFFF0000u);
    float lz = f.z - __uint_as_float(bz & 0xFFFF0000u);
    float lw = f.w - __uint_as_float(bw & 0xFFFF0000u);
    asm("cvt.rn.bf16x2.f32 %0, %1, %2;" : "=r"(lv.x) : "f"(ly), "f"(lx));
    asm("cvt.rn.bf16x2.f32 %0, %1, %2;" : "=r"(lv.y) : "f"(lw), "f"(lz));
}

// ---------------- prep: W pre-split + cursor zero ----------------
__global__ void k_prep(const float* __restrict__ W) {
    if (blockIdx.x == 0 && threadIdx.x < NEXP) g_cursor[threadIdx.x] = 0;
    int e = blockIdx.x >> 2;
    int c = blockIdx.x & 3;
    int tid = threadIdx.x;
    const float* Wc = W + ((size_t)e * DIM + c * CK) * POUT;
#pragma unroll
    for (int i = 0; i < 4; i++) {
        int v = tid + i * 256;
        int kr = v >> 4, nq = v & 15;
        float4 f = *(const float4*)(Wc + (size_t)kr * POUT + nq * 4);
        uint2 hv, lv;
        split4(f, hv, lv);
        uint32_t off = sw128((uint32_t)(kr * 128 + nq * 8));
        *(uint2*)(g_Whi[e][c] + off) = hv;
        *(uint2*)(g_Wlo[e][c] + off) = lv;
    }
}

// ---------------- direct scatter (order within expert is free) ----------------
__global__ void k_scatter(const int* __restrict__ idx) {
    __shared__ int sc[NEXP];
    __shared__ int sbase[NEXP];
    int t = threadIdx.x;
    int lane = t & 31;
    if (t < NEXP) sc[t] = 0;
    __syncthreads();
    int i = blockIdx.x * blockDim.x + t;
    int e = idx[i];
    unsigned mask = __match_any_sync(0xffffffffu, e);
    int leader = __ffs(mask) - 1;
    int base = 0;
    if (lane == leader) base = atomicAdd(&sc[e], __popc(mask));
    base = __shfl_sync(0xffffffffu, base, leader);
    int local = base + __popc(mask & ((1u << lane) - 1u));
    __syncthreads();
    if (t < NEXP && sc[t] > 0) sbase[t] = atomicAdd(&g_cursor[t], sc[t]);
    __syncthreads();
    g_sorted[e][sbase[e] + local] = i;
}

// ---------------- smem layout ----------------
// [0:256)     bias (64 f32)
// [256:1280)  rows (256 int)
// [2048:)     2 x { A_hi 32K | A_lo 32K | B_hi 8K | B_lo 8K }  (2 x 80 KB)
// epilogue:   C tile (256 x 68 f32 = 69.6 KB) overlays buffer 0
#define SM_BIAS 0
#define SM_ROWS 256
#define SM_BUF  2048
#define STAGE   81920
#define SMEM_TOTAL (SM_BUF + 2 * STAGE)   // 165888
#define CS_STRIDE 68

// ---------------- grouped GEMM: BM=256, warp = m32 x n64 ----------------
__global__ void __launch_bounds__(256, 1)
k_gemm_mma(const float* __restrict__ x, const float* __restrict__ bias,
           float* __restrict__ out) {
    // tile -> (expert, m0) via local prefix over final cursors (= counts)
    int tile = blockIdx.x;
    int e = -1, m0 = 0, accT = 0;
#pragma unroll
    for (int i = 0; i < NEXP; i++) {
        int cnt_i = g_cursor[i];
        int nt = (cnt_i + BM - 1) / BM;
        if (e < 0 && tile < accT + nt) { e = i; m0 = (tile - accT) * BM; }
        accT += nt;
    }
    if (e < 0) return;
    int cnt = g_cursor[e];

    extern __shared__ char smem[];
    uint32_t sb = s2u(smem);
    float* bias_s = (float*)(smem + SM_BIAS);
    int*   rows   = (int*)(smem + SM_ROWS);

    int tid = threadIdx.x;
    int wid = tid >> 5, L = tid & 31;

    if (tid < BM) {
        int m = m0 + tid;
        rows[tid] = (m < cnt) ? g_sorted[e][m] : -1;
    }
    if (tid < 16)
        *(float4*)(bias_s + tid * 4) = *(const float4*)(bias + e * POUT + tid * 4);
    __syncthreads();

    // A-load coords: thread covers rows (tid>>4)+16i, fixed q = tid&15
    const int am = tid >> 4;
    const int aq = tid & 15;

    // ldmatrix lane-address components
    int arow = (L & 15);                 // + wid*32 + a*16
    int acol = (L >> 4) * 8;             // bf16 elems, + s*16
    int brow = (L & 7) + ((L >> 3) & 1) * 8;
    int bcol = (L >> 4) * 8;

    float acc[2][8][4];                  // [a(m16 half)][p*2+nhalf][4]
#pragma unroll
    for (int a = 0; a < 2; a++)
#pragma unroll
        for (int j = 0; j < 8; j++)
#pragma unroll
            for (int q = 0; q < 4; q++) acc[a][j][q] = 0.f;

    auto ldg_chunk = [&](int k0, float4 fa[16]) {
#pragma unroll
        for (int i = 0; i < 16; i++) {
            int m = am + i * 16;
            int row = rows[m];
            fa[i] = make_float4(0.f, 0.f, 0.f, 0.f);
            if (row >= 0) fa[i] = *(const float4*)(x + (size_t)row * DIM + k0 + aq * 4);
        }
    };
    auto sts_chunk = [&](const float4 fa[16], uint32_t bufOff) {
#pragma unroll
        for (int i = 0; i < 16; i++) {
            int m = am + i * 16;
            uint2 hv, lv;
            split4(fa[i], hv, lv);
            uint32_t off = sw128((uint32_t)(m * 128 + aq * 8));
            *(uint2*)(smem + bufOff + off) = hv;
            *(uint2*)(smem + bufOff + 32768 + off) = lv;
        }
    };
    auto cp_b = [&](int c, uint32_t bufOff) {
        uint32_t bh = sb + bufOff + 65536;
        uint32_t bl = sb + bufOff + 73728;
        const unsigned char* sh = g_Whi[e][c];
        const unsigned char* sl = g_Wlo[e][c];
#pragma unroll
        for (int i = 0; i < 2; i++) {
            uint32_t o = (uint32_t)(tid + i * 256) * 16;
            cpasync16(bh + o, sh + o);
            cpasync16(bl + o, sl + o);
        }
        asm volatile("cp.async.commit_group;" ::: "memory");
    };

    // ---- prologue: stage chunk 0 into buffer 0 ----
    float4 fa[16];
    cp_b(0, SM_BUF);
    ldg_chunk(0, fa);
    sts_chunk(fa, SM_BUF);
    asm volatile("cp.async.wait_group 0;" ::: "memory");
    __syncthreads();

    for (int c = 0; c < NCH; c++) {
        uint32_t buf  = SM_BUF + (uint32_t)(c & 1) * STAGE;
        uint32_t nbuf = SM_BUF + (uint32_t)((c + 1) & 1) * STAGE;
        const uint32_t AHI = sb + buf, ALO = AHI + 32768;
        const uint32_t BHI = AHI + 65536, BLO = AHI + 73728;

        if (c + 1 < NCH) {
            cp_b(c + 1, nbuf);
            ldg_chunk((c + 1) * CK, fa);
        }

        // ---- MMA phase: warp computes m32 x n64 ----
#pragma unroll
        for (int s = 0; s < 4; s++) {
            uint32_t ah[2][4], al[2][4];
#pragma unroll
            for (int a = 0; a < 2; a++) {
                uint32_t aoff = sw128((uint32_t)((wid * 32 + a * 16 + arow) * 128
                                                 + (s * 16 + acol) * 2));
                ldsm_x4(AHI + aoff, ah[a]);
                ldsm_x4(ALO + aoff, al[a]);
            }
#pragma unroll
            for (int p = 0; p < 4; p++) {
                uint32_t boff = sw128((uint32_t)((s * 16 + brow) * 128
                                                 + (p * 16 + bcol) * 2));
                uint32_t bh[4], bl[4];
                ldsm_x4_t(BHI + boff, bh);
                ldsm_x4_t(BLO + boff, bl);
                // term 1: ah*bh  (4 independent acc chains)
                mma16816(acc[0][2 * p],     ah[0], bh[0], bh[1]);
                mma16816(acc[0][2 * p + 1], ah[0], bh[2], bh[3]);
                mma16816(acc[1][2 * p],     ah[1], bh[0], bh[1]);
                mma16816(acc[1][2 * p + 1], ah[1], bh[2], bh[3]);
                // term 2: al*bh
                mma16816(acc[0][2 * p],     al[0], bh[0], bh[1]);
                mma16816(acc[0][2 * p + 1], al[0], bh[2], bh[3]);
                mma16816(acc[1][2 * p],     al[1], bh[0], bh[1]);
                mma16816(acc[1][2 * p + 1], al[1], bh[2], bh[3]);
                // term 3: ah*bl
                mma16816(acc[0][2 * p],     ah[0], bl[0], bl[1]);
                mma16816(acc[0][2 * p + 1], ah[0], bl[2], bl[3]);
                mma16816(acc[1][2 * p],     ah[1], bl[0], bl[1]);
                mma16816(acc[1][2 * p + 1], ah[1], bl[2], bl[3]);
            }
        }

        if (c + 1 < NCH) {
            sts_chunk(fa, nbuf);
            asm volatile("cp.async.wait_group 0;" ::: "memory");
        }
        __syncthreads();
    }

    // ---- epilogue: transpose through smem, coalesced scatter ----
    float* Cs = (float*)(smem + SM_BUF);
#pragma unroll
    for (int a = 0; a < 2; a++) {
        int r = wid * 32 + a * 16 + (L >> 2);
        int cbase = (L & 3) * 2;
#pragma unroll
        for (int j = 0; j < 8; j++) {
            int cc = cbase + j * 8;
            *(float2*)(Cs + r * CS_STRIDE + cc)       = make_float2(acc[a][j][0], acc[a][j][1]);
            *(float2*)(Cs + (r + 8) * CS_STRIDE + cc) = make_float2(acc[a][j][2], acc[a][j][3]);
        }
    }
    __syncthreads();
#pragma unroll
    for (int rb = 0; rb < 2; rb++) {
        int r = rb * 128 + (tid >> 1);
        int half = tid & 1;
        int row = rows[r];
        if (row >= 0) {
            float* op = out + (size_t)row * POUT;
#pragma unroll
            for (int q = 0; q < 8; q++) {
                int c4 = half * 8 + q;
                float4 v = *(float4*)(Cs + r * CS_STRIDE + c4 * 4);
                float4 bv = *(float4*)(bias_s + c4 * 4);
                v.x += bv.x; v.y += bv.y; v.z += bv.z; v.w += bv.w;
                *(float4*)(op + c4 * 4) = v;
            }
        }
    }
}

// ---------------- launch ----------------
extern "C" void kernel_launch(void* const* d_in, const int* in_sizes, int n_in,
                              void* d_out, int out_size) {
    const float* x   = (const float*)d_in[0];  // [32,8192,256]
    const float* W   = (const float*)d_in[1];  // [16,256,64]
    const float* b   = (const float*)d_in[2];  // [16,64]
    const int*   idx = (const int*)d_in[3];    // [32,8192]
    float* out = (float*)d_out;                // [32,8192,64]

    cudaFuncSetAttribute(k_gemm_mma, cudaFuncAttributeMaxDynamicSharedMemorySize, SMEM_TOTAL);

    k_prep<<<NEXP * NCH, 256>>>(W);
    k_scatter<<<NTOK / 256, 256>>>(idx);

    int max_tiles = NTOK / BM + NEXP;
    k_gemm_mma<<<max_tiles, 256, SMEM_TOTAL>>>(x, b, out);
}

// round 8
// speedup vs baseline: 1.6031x; 1.6031x over previous
#include <cuda_runtime.h>
#include <cuda_bf16.h>
#include <cstdint>

// Problem constants (fixed shapes per reference)
#define NTOK  (32 * 8192)   // 262144 tokens
#define DIM   256           // K
#define NEXP  16
#define POUT  64            // N
#define BM    128           // tokens per tile
#define CK    64            // K per chunk
#define NCH   (DIM / CK)    // 4 chunks

// ---------------- scratch ----------------
__device__ int g_sorted[NEXP][NTOK];   // per-expert slot regions
__device__ int g_cursor[NEXP];
// Pre-split W tiles, bf16 hi/lo, in swizzled tile byte order.
__device__ unsigned char g_Whi[NEXP][NCH][8192];
__device__ unsigned char g_Wlo[NEXP][NCH][8192];

// ---------------- helpers ----------------
__device__ __forceinline__ uint32_t s2u(const void* p) {
    uint32_t a;
    asm("{ .reg .u64 t; cvta.to.shared.u64 t, %1; cvt.u32.u64 %0, t; }" : "=r"(a) : "l"(p));
    return a;
}
__device__ __forceinline__ uint32_t sw128(uint32_t o) { return o ^ ((o >> 3) & 0x70); }

__device__ __forceinline__ void ldsm_x4(uint32_t addr, uint32_t r[4]) {
    asm volatile("ldmatrix.sync.aligned.m8n8.x4.shared.b16 {%0,%1,%2,%3}, [%4];"
                 : "=r"(r[0]), "=r"(r[1]), "=r"(r[2]), "=r"(r[3]) : "r"(addr));
}
__device__ __forceinline__ void ldsm_x4_t(uint32_t addr, uint32_t r[4]) {
    asm volatile("ldmatrix.sync.aligned.m8n8.x4.trans.shared.b16 {%0,%1,%2,%3}, [%4];"
                 : "=r"(r[0]), "=r"(r[1]), "=r"(r[2]), "=r"(r[3]) : "r"(addr));
}
__device__ __forceinline__ void mma16816(float c[4], const uint32_t a[4],
                                         uint32_t b0, uint32_t b1) {
    asm volatile(
        "mma.sync.aligned.m16n8k16.row.col.f32.bf16.bf16.f32 "
        "{%0,%1,%2,%3}, {%4,%5,%6,%7}, {%8,%9}, {%0,%1,%2,%3};"
        : "+f"(c[0]), "+f"(c[1]), "+f"(c[2]), "+f"(c[3])
        : "r"(a[0]), "r"(a[1]), "r"(a[2]), "r"(a[3]), "r"(b0), "r"(b1));
}
__device__ __forceinline__ void cpasync16(uint32_t dst, const void* src) {
    asm volatile("cp.async.cg.shared.global [%0], [%1], 16;"
                 :: "r"(dst), "l"(src) : "memory");
}

// split fp32 float4 -> packed bf16 hi (truncated, exact bits) + bf16 lo (residual)
__device__ __forceinline__ void split4(float4 f, uint2& hv, uint2& lv) {
    uint32_t bx = __float_as_uint(f.x), by = __float_as_uint(f.y);
    uint32_t bz = __float_as_uint(f.z), bw = __float_as_uint(f.w);
    hv.x = __byte_perm(bx, by, 0x7632);
    hv.y = __byte_perm(bz, bw, 0x7632);
    float lx = f.x - __uint_as_float(bx & 0xFFFF0000u);
    float ly = f.y - __uint_as_float(by & 0xFFFF0000u);
    float lz = f.z - __uint_as_float(bz & 0xFFFF0000u);
    float lw = f.w - __uint_as_float(bw & 0xFFFF0000u);
    asm("cvt.rn.bf16x2.f32 %0, %1, %2;" : "=r"(lv.x) : "f"(ly), "f"(lx));
    asm("cvt.rn.bf16x2.f32 %0, %1, %2;" : "=r"(lv.y) : "f"(lw), "f"(lz));
}

// ---------------- prep: W pre-split + cursor zero ----------------
__global__ void k_prep(const float* __restrict__ W) {
    if (blockIdx.x == 0 && threadIdx.x < NEXP) g_cursor[threadIdx.x] = 0;
    int e = blockIdx.x >> 2;
    int c = blockIdx.x & 3;
    int tid = threadIdx.x;
    const float* Wc = W + ((size_t)e * DIM + c * CK) * POUT;
#pragma unroll
    for (int i = 0; i < 4; i++) {
        int v = tid + i * 256;
        int kr = v >> 4, nq = v & 15;
        float4 f = *(const float4*)(Wc + (size_t)kr * POUT + nq * 4);
        uint2 hv, lv;
        split4(f, hv, lv);
        uint32_t off = sw128((uint32_t)(kr * 128 + nq * 8));
        *(uint2*)(g_Whi[e][c] + off) = hv;
        *(uint2*)(g_Wlo[e][c] + off) = lv;
    }
}

// ---------------- direct scatter (order within expert is free) ----------------
__global__ void k_scatter(const int* __restrict__ idx) {
    __shared__ int sc[NEXP];
    __shared__ int sbase[NEXP];
    int t = threadIdx.x;
    int lane = t & 31;
    if (t < NEXP) sc[t] = 0;
    __syncthreads();
    int i = blockIdx.x * blockDim.x + t;
    int e = idx[i];
    unsigned mask = __match_any_sync(0xffffffffu, e);
    int leader = __ffs(mask) - 1;
    int base = 0;
    if (lane == leader) base = atomicAdd(&sc[e], __popc(mask));
    base = __shfl_sync(0xffffffffu, base, leader);
    int local = base + __popc(mask & ((1u << lane) - 1u));
    __syncthreads();
    if (t < NEXP && sc[t] > 0) sbase[t] = atomicAdd(&g_cursor[t], sc[t]);
    __syncthreads();
    g_sorted[e][sbase[e] + local] = i;
}

// ---------------- smem layout ----------------
// [0:256)    bias (64 f32)
// [256:768)  rows (128 int)
// [1024:)    2 x { A_hi 16K | A_lo 16K | B_hi 8K | B_lo 8K }  (2 x 48 KB)
// epilogue:  C tile (128 x 68 f32 = 34.8 KB) overlays buffer 0
#define SM_BIAS 0
#define SM_ROWS 256
#define SM_BUF  1024
#define STAGE   49152
#define SMEM_TOTAL (SM_BUF + 2 * STAGE)   // 99328
#define CS_STRIDE 68

// ---------------- grouped GEMM via mma.sync bf16 split (BM=128, 2 CTA/SM) ----
__global__ void __launch_bounds__(256, 2)
k_gemm_mma(const float* __restrict__ x, const float* __restrict__ bias,
           float* __restrict__ out) {
    // tile -> (expert, m0) via local prefix over final cursors (= counts)
    int tile = blockIdx.x;
    int e = -1, m0 = 0, accT = 0;
#pragma unroll
    for (int i = 0; i < NEXP; i++) {
        int cnt_i = g_cursor[i];
        int nt = (cnt_i + BM - 1) / BM;
        if (e < 0 && tile < accT + nt) { e = i; m0 = (tile - accT) * BM; }
        accT += nt;
    }
    if (e < 0) return;
    int cnt = g_cursor[e];

    extern __shared__ char smem[];
    uint32_t sb = s2u(smem);
    float* bias_s = (float*)(smem + SM_BIAS);
    int*   rows   = (int*)(smem + SM_ROWS);

    int tid = threadIdx.x;
    int wid = tid >> 5, L = tid & 31;

    if (tid < BM) {
        int m = m0 + tid;
        rows[tid] = (m < cnt) ? g_sorted[e][m] : -1;
    }
    if (tid < 16)
        *(float4*)(bias_s + tid * 4) = *(const float4*)(bias + e * POUT + tid * 4);
    __syncthreads();

    // per-thread A-load coords
    const int am = tid >> 4;
    const int aq = tid & 15;

    // ldmatrix lane-address components (bytes, pre-swizzle)
    int arow = wid * 16 + (L & 7) + ((L >> 3) & 1) * 8;
    int acol = (L >> 4) * 8;
    int brow = (L & 7) + ((L >> 3) & 1) * 8;
    int bcol = (L >> 4) * 8;

    float acc[8][4];
#pragma unroll
    for (int j = 0; j < 8; j++)
#pragma unroll
        for (int q = 0; q < 4; q++) acc[j][q] = 0.f;

    auto ldg_chunk = [&](int k0, float4 fa[8]) {
#pragma unroll
        for (int i = 0; i < 8; i++) {
            int m = am + i * 16;
            int row = rows[m];
            fa[i] = make_float4(0.f, 0.f, 0.f, 0.f);
            if (row >= 0) fa[i] = *(const float4*)(x + (size_t)row * DIM + k0 + aq * 4);
        }
    };
    auto sts_chunk = [&](const float4 fa[8], uint32_t bufOff) {
#pragma unroll
        for (int i = 0; i < 8; i++) {
            int m = am + i * 16;
            uint2 hv, lv;
            split4(fa[i], hv, lv);
            uint32_t off = sw128((uint32_t)(m * 128 + aq * 8));
            *(uint2*)(smem + bufOff + off) = hv;
            *(uint2*)(smem + bufOff + 16384 + off) = lv;
        }
    };
    auto cp_b = [&](int c, uint32_t bufOff) {
        uint32_t bh = sb + bufOff + 32768;
        uint32_t bl = sb + bufOff + 40960;
        const unsigned char* sh = g_Whi[e][c];
        const unsigned char* sl = g_Wlo[e][c];
#pragma unroll
        for (int i = 0; i < 2; i++) {
            uint32_t o = (uint32_t)(tid + i * 256) * 16;
            cpasync16(bh + o, sh + o);
            cpasync16(bl + o, sl + o);
        }
        asm volatile("cp.async.commit_group;" ::: "memory");
    };

    // ---- prologue: stage chunk 0 into buffer 0 ----
    float4 fa[8];
    cp_b(0, SM_BUF);
    ldg_chunk(0, fa);
    sts_chunk(fa, SM_BUF);
    asm volatile("cp.async.wait_group 0;" ::: "memory");
    __syncthreads();

    for (int c = 0; c < NCH; c++) {
        uint32_t buf  = SM_BUF + (uint32_t)(c & 1) * STAGE;
        uint32_t nbuf = SM_BUF + (uint32_t)((c + 1) & 1) * STAGE;
        const uint32_t AHI = sb + buf, ALO = AHI + 16384;
        const uint32_t BHI = AHI + 32768, BLO = AHI + 40960;

        if (c + 1 < NCH) {
            cp_b(c + 1, nbuf);
            ldg_chunk((c + 1) * CK, fa);
        }

        // ---- MMA phase on current buffer ----
#pragma unroll
        for (int s = 0; s < 4; s++) {
            uint32_t aoff = sw128((uint32_t)(arow * 128 + (s * 16 + acol) * 2));
            uint32_t ah[4], al[4];
            ldsm_x4(AHI + aoff, ah);
            ldsm_x4(ALO + aoff, al);
#pragma unroll
            for (int p = 0; p < 4; p++) {
                uint32_t boff = sw128((uint32_t)((s * 16 + brow) * 128 + (p * 16 + bcol) * 2));
                uint32_t bh[4], bl[4];
                ldsm_x4_t(BHI + boff, bh);
                ldsm_x4_t(BLO + boff, bl);
                mma16816(acc[2 * p],     ah, bh[0], bh[1]);
                mma16816(acc[2 * p + 1], ah, bh[2], bh[3]);
                mma16816(acc[2 * p],     al, bh[0], bh[1]);
                mma16816(acc[2 * p + 1], al, bh[2], bh[3]);
                mma16816(acc[2 * p],     ah, bl[0], bl[1]);
                mma16816(acc[2 * p + 1], ah, bl[2], bl[3]);
            }
        }

        // ---- stage next chunk's A into other buffer (overlaps others' MMA) ----
        if (c + 1 < NCH) {
            sts_chunk(fa, nbuf);
            asm volatile("cp.async.wait_group 0;" ::: "memory");
        }
        __syncthreads();
    }

    // ---- epilogue: transpose through smem, coalesced scatter ----
    float* Cs = (float*)(smem + SM_BUF);
    {
        int r = wid * 16 + (L >> 2);
        int cbase = (L & 3) * 2;
#pragma unroll
        for (int j = 0; j < 8; j++) {
            int cc = cbase + j * 8;
            *(float2*)(Cs + r * CS_STRIDE + cc)       = make_float2(acc[j][0], acc[j][1]);
            *(float2*)(Cs + (r + 8) * CS_STRIDE + cc) = make_float2(acc[j][2], acc[j][3]);
        }
    }
    __syncthreads();
    {
        int r = tid >> 1;
        int half = tid & 1;
        int row = rows[r];
        if (row >= 0) {
            float* op = out + (size_t)row * POUT;
#pragma unroll
            for (int q = 0; q < 8; q++) {
                int c4 = half * 8 + q;
                float4 v = *(float4*)(Cs + r * CS_STRIDE + c4 * 4);
                float4 bv = *(float4*)(bias_s + c4 * 4);
                v.x += bv.x; v.y += bv.y; v.z += bv.z; v.w += bv.w;
                *(float4*)(op + c4 * 4) = v;
            }
        }
    }
}

// ---------------- launch ----------------
extern "C" void kernel_launch(void* const* d_in, const int* in_sizes, int n_in,
                              void* d_out, int out_size) {
    const float* x   = (const float*)d_in[0];  // [32,8192,256]
    const float* W   = (const float*)d_in[1];  // [16,256,64]
    const float* b   = (const float*)d_in[2];  // [16,64]
    const int*   idx = (const int*)d_in[3];    // [32,8192]
    float* out = (float*)d_out;                // [32,8192,64]

    cudaFuncSetAttribute(k_gemm_mma, cudaFuncAttributeMaxDynamicSharedMemorySize, SMEM_TOTAL);

    k_prep<<<NEXP * NCH, 256>>>(W);
    k_scatter<<<NTOK / 256, 256>>>(idx);

    int max_tiles = NTOK / BM + NEXP;
    k_gemm_mma<<<max_tiles, 256, SMEM_TOTAL>>>(x, b, out);
}

// round 9
// speedup vs baseline: 1.6659x; 1.0392x over previous
#include <cuda_runtime.h>
#include <cuda_bf16.h>
#include <cstdint>

// Problem constants (fixed shapes per reference)
#define NTOK  (32 * 8192)   // 262144 tokens
#define DIM   256           // K
#define NEXP  16
#define POUT  64            // N
#define BM    128           // tokens per tile
#define CK    64            // K per chunk
#define NCH   (DIM / CK)    // 4 chunks

// ---------------- scratch ----------------
__device__ int g_sorted[NEXP][NTOK];   // per-expert slot regions
__device__ int g_cursor[NEXP];
// Pre-split W tiles, bf16 hi/lo, in swizzled tile byte order.
__device__ unsigned char g_Whi[NEXP][NCH][8192];
__device__ unsigned char g_Wlo[NEXP][NCH][8192];

// ---------------- helpers ----------------
__device__ __forceinline__ uint32_t s2u(const void* p) {
    uint32_t a;
    asm("{ .reg .u64 t; cvta.to.shared.u64 t, %1; cvt.u32.u64 %0, t; }" : "=r"(a) : "l"(p));
    return a;
}
__device__ __forceinline__ uint32_t sw128(uint32_t o) { return o ^ ((o >> 3) & 0x70); }

__device__ __forceinline__ void ldsm_x4(uint32_t addr, uint32_t r[4]) {
    asm volatile("ldmatrix.sync.aligned.m8n8.x4.shared.b16 {%0,%1,%2,%3}, [%4];"
                 : "=r"(r[0]), "=r"(r[1]), "=r"(r[2]), "=r"(r[3]) : "r"(addr));
}
__device__ __forceinline__ void ldsm_x4_t(uint32_t addr, uint32_t r[4]) {
    asm volatile("ldmatrix.sync.aligned.m8n8.x4.trans.shared.b16 {%0,%1,%2,%3}, [%4];"
                 : "=r"(r[0]), "=r"(r[1]), "=r"(r[2]), "=r"(r[3]) : "r"(addr));
}
__device__ __forceinline__ void mma16816(float c[4], const uint32_t a[4],
                                         uint32_t b0, uint32_t b1) {
    asm volatile(
        "mma.sync.aligned.m16n8k16.row.col.f32.bf16.bf16.f32 "
        "{%0,%1,%2,%3}, {%4,%5,%6,%7}, {%8,%9}, {%0,%1,%2,%3};"
        : "+f"(c[0]), "+f"(c[1]), "+f"(c[2]), "+f"(c[3])
        : "r"(a[0]), "r"(a[1]), "r"(a[2]), "r"(a[3]), "r"(b0), "r"(b1));
}
__device__ __forceinline__ void cpasync16(uint32_t dst, const void* src) {
    asm volatile("cp.async.cg.shared.global [%0], [%1], 16;"
                 :: "r"(dst), "l"(src) : "memory");
}

// split fp32 float4 -> packed bf16 hi (truncated, exact bits) + bf16 lo (residual)
__device__ __forceinline__ void split4(float4 f, uint2& hv, uint2& lv) {
    uint32_t bx = __float_as_uint(f.x), by = __float_as_uint(f.y);
    uint32_t bz = __float_as_uint(f.z), bw = __float_as_uint(f.w);
    hv.x = __byte_perm(bx, by, 0x7632);
    hv.y = __byte_perm(bz, bw, 0x7632);
    float lx = f.x - __uint_as_float(bx & 0xFFFF0000u);
    float ly = f.y - __uint_as_float(by & 0xFFFF0000u);
    float lz = f.z - __uint_as_float(bz & 0xFFFF0000u);
    float lw = f.w - __uint_as_float(bw & 0xFFFF0000u);
    asm("cvt.rn.bf16x2.f32 %0, %1, %2;" : "=r"(lv.x) : "f"(ly), "f"(lx));
    asm("cvt.rn.bf16x2.f32 %0, %1, %2;" : "=r"(lv.y) : "f"(lw), "f"(lz));
}

// ---------------- prep: W pre-split + cursor zero ----------------
__global__ void k_prep(const float* __restrict__ W) {
    if (blockIdx.x == 0 && threadIdx.x < NEXP) g_cursor[threadIdx.x] = 0;
    int e = blockIdx.x >> 2;
    int c = blockIdx.x & 3;
    int tid = threadIdx.x;
    const float* Wc = W + ((size_t)e * DIM + c * CK) * POUT;
#pragma unroll
    for (int i = 0; i < 4; i++) {
        int v = tid + i * 256;
        int kr = v >> 4, nq = v & 15;
        float4 f = *(const float4*)(Wc + (size_t)kr * POUT + nq * 4);
        uint2 hv, lv;
        split4(f, hv, lv);
        uint32_t off = sw128((uint32_t)(kr * 128 + nq * 8));
        *(uint2*)(g_Whi[e][c] + off) = hv;
        *(uint2*)(g_Wlo[e][c] + off) = lv;
    }
}

// ---------------- direct scatter (order within expert is free) ----------------
__global__ void k_scatter(const int* __restrict__ idx) {
    __shared__ int sc[NEXP];
    __shared__ int sbase[NEXP];
    int t = threadIdx.x;
    int lane = t & 31;
    if (t < NEXP) sc[t] = 0;
    __syncthreads();
    int i = blockIdx.x * blockDim.x + t;
    int e = idx[i];
    unsigned mask = __match_any_sync(0xffffffffu, e);
    int leader = __ffs(mask) - 1;
    int base = 0;
    if (lane == leader) base = atomicAdd(&sc[e], __popc(mask));
    base = __shfl_sync(0xffffffffu, base, leader);
    int local = base + __popc(mask & ((1u << lane) - 1u));
    __syncthreads();
    if (t < NEXP && sc[t] > 0) sbase[t] = atomicAdd(&g_cursor[t], sc[t]);
    __syncthreads();
    g_sorted[e][sbase[e] + local] = i;
}

// ---------------- smem layout ----------------
// [0:256)    bias (64 f32)
// [256:768)  rows (128 int)
// [1024:)    2 x { A_hi 16K | A_lo 16K | B_hi 8K | B_lo 8K }  (2 x 48 KB)
// epilogue:  C tile (128 x 68 f32 = 34.8 KB) overlays buffer 0
#define SM_BIAS 0
#define SM_ROWS 256
#define SM_BUF  1024
#define STAGE   49152
#define SMEM_TOTAL (SM_BUF + 2 * STAGE)   // 99328
#define CS_STRIDE 68

// ---------------- grouped GEMM: BM=128, warp = m32 x n32, 2 CTA/SM --------
__global__ void __launch_bounds__(256, 2)
k_gemm_mma(const float* __restrict__ x, const float* __restrict__ bias,
           float* __restrict__ out) {
    // tile -> (expert, m0) via local prefix over final cursors (= counts)
    int tile = blockIdx.x;
    int e = -1, m0 = 0, accT = 0;
#pragma unroll
    for (int i = 0; i < NEXP; i++) {
        int cnt_i = g_cursor[i];
        int nt = (cnt_i + BM - 1) / BM;
        if (e < 0 && tile < accT + nt) { e = i; m0 = (tile - accT) * BM; }
        accT += nt;
    }
    if (e < 0) return;
    int cnt = g_cursor[e];

    extern __shared__ char smem[];
    uint32_t sb = s2u(smem);
    float* bias_s = (float*)(smem + SM_BIAS);
    int*   rows   = (int*)(smem + SM_ROWS);

    int tid = threadIdx.x;
    int wid = tid >> 5, L = tid & 31;

    if (tid < BM) {
        int m = m0 + tid;
        rows[tid] = (m < cnt) ? g_sorted[e][m] : -1;
    }
    if (tid < 16)
        *(float4*)(bias_s + tid * 4) = *(const float4*)(bias + e * POUT + tid * 4);
    __syncthreads();

    // per-thread A-load coords
    const int am = tid >> 4;
    const int aq = tid & 15;

    // warp tile: m32 x n32  (warp grid 4 x 2 over 128 x 64)
    const int mrow  = (wid & 3) * 32;
    const int nbase = (wid >> 2) * 32;

    // ldmatrix lane-address components (pre-swizzle)
    int arow = (L & 15);                 // + mrow + a*16
    int acol = (L >> 4) * 8;             // bf16 elems, + s*16
    int brow = (L & 7) + ((L >> 3) & 1) * 8;
    int bcol = (L >> 4) * 8;             // + nbase + p*16

    float acc[2][4][4];                  // [m-half][n8 group][4]
#pragma unroll
    for (int a = 0; a < 2; a++)
#pragma unroll
        for (int j = 0; j < 4; j++)
#pragma unroll
            for (int q = 0; q < 4; q++) acc[a][j][q] = 0.f;

    auto ldg_chunk = [&](int k0, float4 fa[8]) {
#pragma unroll
        for (int i = 0; i < 8; i++) {
            int m = am + i * 16;
            int row = rows[m];
            fa[i] = make_float4(0.f, 0.f, 0.f, 0.f);
            if (row >= 0) fa[i] = *(const float4*)(x + (size_t)row * DIM + k0 + aq * 4);
        }
    };
    auto sts_chunk = [&](const float4 fa[8], uint32_t bufOff) {
#pragma unroll
        for (int i = 0; i < 8; i++) {
            int m = am + i * 16;
            uint2 hv, lv;
            split4(fa[i], hv, lv);
            uint32_t off = sw128((uint32_t)(m * 128 + aq * 8));
            *(uint2*)(smem + bufOff + off) = hv;
            *(uint2*)(smem + bufOff + 16384 + off) = lv;
        }
    };
    auto cp_b = [&](int c, uint32_t bufOff) {
        uint32_t bh = sb + bufOff + 32768;
        uint32_t bl = sb + bufOff + 40960;
        const unsigned char* sh = g_Whi[e][c];
        const unsigned char* sl = g_Wlo[e][c];
#pragma unroll
        for (int i = 0; i < 2; i++) {
            uint32_t o = (uint32_t)(tid + i * 256) * 16;
            cpasync16(bh + o, sh + o);
            cpasync16(bl + o, sl + o);
        }
        asm volatile("cp.async.commit_group;" ::: "memory");
    };

    // ---- prologue: stage chunk 0 into buffer 0 ----
    float4 fa[8];
    cp_b(0, SM_BUF);
    ldg_chunk(0, fa);
    sts_chunk(fa, SM_BUF);
    asm volatile("cp.async.wait_group 0;" ::: "memory");
    __syncthreads();

    for (int c = 0; c < NCH; c++) {
        uint32_t buf  = SM_BUF + (uint32_t)(c & 1) * STAGE;
        uint32_t nbuf = SM_BUF + (uint32_t)((c + 1) & 1) * STAGE;
        const uint32_t AHI = sb + buf, ALO = AHI + 16384;
        const uint32_t BHI = AHI + 32768, BLO = AHI + 40960;

        if (c + 1 < NCH) {
            cp_b(c + 1, nbuf);
            ldg_chunk((c + 1) * CK, fa);
        }

        // ---- MMA phase: warp computes m32 x n32 ----
#pragma unroll
        for (int s = 0; s < 4; s++) {
            uint32_t ah[2][4], al[2][4];
#pragma unroll
            for (int a = 0; a < 2; a++) {
                uint32_t aoff = sw128((uint32_t)((mrow + a * 16 + arow) * 128
                                                 + (s * 16 + acol) * 2));
                ldsm_x4(AHI + aoff, ah[a]);
                ldsm_x4(ALO + aoff, al[a]);
            }
            uint32_t bh[2][4], bl[2][4];
#pragma unroll
            for (int p = 0; p < 2; p++) {
                uint32_t boff = sw128((uint32_t)((s * 16 + brow) * 128
                                                 + (nbase + p * 16 + bcol) * 2));
                ldsm_x4_t(BHI + boff, bh[p]);
                ldsm_x4_t(BLO + boff, bl[p]);
            }
            // term 1: ah*bh  (8 independent chains)
#pragma unroll
            for (int a = 0; a < 2; a++)
#pragma unroll
                for (int p = 0; p < 2; p++) {
                    mma16816(acc[a][2 * p],     ah[a], bh[p][0], bh[p][1]);
                    mma16816(acc[a][2 * p + 1], ah[a], bh[p][2], bh[p][3]);
                }
            // term 2: al*bh
#pragma unroll
            for (int a = 0; a < 2; a++)
#pragma unroll
                for (int p = 0; p < 2; p++) {
                    mma16816(acc[a][2 * p],     al[a], bh[p][0], bh[p][1]);
                    mma16816(acc[a][2 * p + 1], al[a], bh[p][2], bh[p][3]);
                }
            // term 3: ah*bl
#pragma unroll
            for (int a = 0; a < 2; a++)
#pragma unroll
                for (int p = 0; p < 2; p++) {
                    mma16816(acc[a][2 * p],     ah[a], bl[p][0], bl[p][1]);
                    mma16816(acc[a][2 * p + 1], ah[a], bl[p][2], bl[p][3]);
                }
        }

        // ---- stage next chunk's A into other buffer (overlaps others' MMA) ----
        if (c + 1 < NCH) {
            sts_chunk(fa, nbuf);
            asm volatile("cp.async.wait_group 0;" ::: "memory");
        }
        __syncthreads();
    }

    // ---- epilogue: transpose through smem, coalesced scatter ----
    float* Cs = (float*)(smem + SM_BUF);
#pragma unroll
    for (int a = 0; a < 2; a++) {
        int r = mrow + a * 16 + (L >> 2);
        int cbase = nbase + (L & 3) * 2;
#pragma unroll
        for (int j = 0; j < 4; j++) {
            int cc = cbase + j * 8;
            *(float2*)(Cs + r * CS_STRIDE + cc)       = make_float2(acc[a][j][0], acc[a][j][1]);
            *(float2*)(Cs + (r + 8) * CS_STRIDE + cc) = make_float2(acc[a][j][2], acc[a][j][3]);
        }
    }
    __syncthreads();
    {
        int r = tid >> 1;
        int half = tid & 1;
        int row = rows[r];
        if (row >= 0) {
            float* op = out + (size_t)row * POUT;
#pragma unroll
            for (int q = 0; q < 8; q++) {
                int c4 = half * 8 + q;
                float4 v = *(float4*)(Cs + r * CS_STRIDE + c4 * 4);
                float4 bv = *(float4*)(bias_s + c4 * 4);
                v.x += bv.x; v.y += bv.y; v.z += bv.z; v.w += bv.w;
                *(float4*)(op + c4 * 4) = v;
            }
        }
    }
}

// ---------------- launch ----------------
extern "C" void kernel_launch(void* const* d_in, const int* in_sizes, int n_in,
                              void* d_out, int out_size) {
    const float* x   = (const float*)d_in[0];  // [32,8192,256]
    const float* W   = (const float*)d_in[1];  // [16,256,64]
    const float* b   = (const float*)d_in[2];  // [16,64]
    const int*   idx = (const int*)d_in[3];    // [32,8192]
    float* out = (float*)d_out;                // [32,8192,64]

    cudaFuncSetAttribute(k_gemm_mma, cudaFuncAttributeMaxDynamicSharedMemorySize, SMEM_TOTAL);

    k_prep<<<NEXP * NCH, 256>>>(W);
    k_scatter<<<NTOK / 256, 256>>>(idx);

    int max_tiles = NTOK / BM + NEXP;
    k_gemm_mma<<<max_tiles, 256, SMEM_TOTAL>>>(x, b, out);
}